// round 16
// baseline (speedup 1.0000x reference)
#include <cuda_runtime.h>
#include <cuda_bf16.h>
#include <stdint.h>

#define BATCH 2
#define SEQ   2048
#define DIM   1024
#define NH    16
#define HD    64
#define MTOT  (BATCH*SEQ)   // 4096

// GEMM: CTA 128x128x32, 2-stage cp.async pipeline
#define GBM 128
#define GBN 128
#define GBK 32
#define GPB  80                 // smem row pitch bytes (32 bf16 data + 16B pad): (5r)%8 distinct
#define APLB (GBM*GPB)          // plane bytes 10240
#define GSTAGEB (4*APLB)        // Ah,Al,Bh,Bl = 40960 B

// Attention: 128-row q tile, 64-key kv tiles, 2-stage cp.async
#define QT 128
#define APB  144                // kv plane row pitch bytes (64 bf16 + 16B pad): r%8 distinct
#define KPLB (64*APB)           // 9216 B per plane
#define ASTAGEB (4*KPLB)        // Kh,Kl,Vh,Vl = 36864 B

// bf16 hi/lo planes (allocation-free rule: device globals)
__device__ __nv_bfloat16 g_xh[MTOT*DIM], g_xl[MTOT*DIM];
__device__ __nv_bfloat16 g_wh[4*DIM*DIM], g_wl[4*DIM*DIM];
__device__ __nv_bfloat16 g_qh[MTOT*DIM], g_ql[MTOT*DIM];
__device__ __nv_bfloat16 g_kh[MTOT*DIM], g_kl[MTOT*DIM];
__device__ __nv_bfloat16 g_vh[MTOT*DIM], g_vl[MTOT*DIM];
__device__ __nv_bfloat16 g_oh[MTOT*DIM], g_ol[MTOT*DIM];

// ---------------------------------------------------------------------------
__device__ __forceinline__ void splitpair(float e0, float e1, uint32_t& h, uint32_t& l) {
    __nv_bfloat16 h0 = __float2bfloat16(e0);
    __nv_bfloat16 h1 = __float2bfloat16(e1);
    __nv_bfloat162 hp = __halves2bfloat162(h0, h1);
    h = *reinterpret_cast<uint32_t*>(&hp);
    __nv_bfloat162 lp = __floats2bfloat162_rn(e0 - __bfloat162float(h0),
                                              e1 - __bfloat162float(h1));
    l = *reinterpret_cast<uint32_t*>(&lp);
}
__device__ __forceinline__ void split4k(float4 v, uint2& h, uint2& l) {
    splitpair(v.x, v.y, h.x, l.x);
    splitpair(v.z, v.w, h.y, l.y);
}

#define MMA_BF16(c, a, b)                                                      \
    asm volatile(                                                              \
        "mma.sync.aligned.m16n8k16.row.col.f32.bf16.bf16.f32 "                 \
        "{%0,%1,%2,%3}, {%4,%5,%6,%7}, {%8,%9}, {%0,%1,%2,%3};"                \
        : "+f"((c)[0]), "+f"((c)[1]), "+f"((c)[2]), "+f"((c)[3])               \
        : "r"((a)[0]), "r"((a)[1]), "r"((a)[2]), "r"((a)[3]),                  \
          "r"((b)[0]), "r"((b)[1]))

__device__ __forceinline__ void ldm_x4(uint32_t* r, uint32_t a) {
    asm volatile("ldmatrix.sync.aligned.m8n8.x4.shared.b16 {%0,%1,%2,%3}, [%4];"
        : "=r"(r[0]), "=r"(r[1]), "=r"(r[2]), "=r"(r[3]) : "r"(a));
}
__device__ __forceinline__ void ldm_x4t(uint32_t* r, uint32_t a) {
    asm volatile("ldmatrix.sync.aligned.m8n8.x4.trans.shared.b16 {%0,%1,%2,%3}, [%4];"
        : "=r"(r[0]), "=r"(r[1]), "=r"(r[2]), "=r"(r[3]) : "r"(a));
}
__device__ __forceinline__ void cp16(uint32_t s, const void* g) {
    asm volatile("cp.async.cg.shared.global [%0], [%1], 16;" :: "r"(s), "l"(g));
}
#define CP_COMMIT() asm volatile("cp.async.commit_group;")
#define CP_WAIT0()  asm volatile("cp.async.wait_group 0;")

// ---------------------------------------------------------------------------
// Prep (single launch): fp32 -> bf16 hi/lo planes for x and all 4 weights.
// ---------------------------------------------------------------------------
#define NX4 (MTOT*DIM/4)
#define NW4 (DIM*DIM/4)
__global__ void split_all_kernel(
    const float* __restrict__ x,
    const float* __restrict__ Wq, const float* __restrict__ Wk,
    const float* __restrict__ Wv, const float* __restrict__ Wo,
    uint2* __restrict__ xh, uint2* __restrict__ xl,
    uint2* __restrict__ wh, uint2* __restrict__ wl)
{
    int i = blockIdx.x * blockDim.x + threadIdx.x;
    const float4* src;
    uint2 *ho, *lo;
    int off;
    if (i < NX4) {
        src = (const float4*)x; off = i; ho = xh; lo = xl;
    } else {
        int j = i - NX4;
        int w = j / NW4;
        off = j - w * NW4;
        src = (const float4*)(w == 0 ? Wq : w == 1 ? Wk : w == 2 ? Wv : Wo);
        ho = wh + (size_t)w * NW4;
        lo = wl + (size_t)w * NW4;
    }
    float4 v = src[off];
    uint2 hw, lw; split4k(v, hw, lw);
    ho[off] = hw;
    lo[off] = lw;
}

// ---------------------------------------------------------------------------
// GEMM C[M,N] = A[M,K] @ W[N,K]^T (+bias) via 3xBF16 mma.sync on hi/lo planes.
// MODE 0: out = bf16 hi/lo planes of (acc+bias)*scale, grid.z selects q/k/v.
// MODE 1: out = fp32 (acc+bias).
// ---------------------------------------------------------------------------
template<int MODE>
__global__ __launch_bounds__(256, 2) void gemm_planes_kernel(
    const __nv_bfloat16* __restrict__ Ah, const __nv_bfloat16* __restrict__ Al,
    const __nv_bfloat16* __restrict__ Wh, const __nv_bfloat16* __restrict__ Wl,
    const float* __restrict__ bq, const float* __restrict__ bk, const float* __restrict__ bv,
    uint32_t* __restrict__ oh0, uint32_t* __restrict__ ol0,
    uint32_t* __restrict__ oh1, uint32_t* __restrict__ ol1,
    uint32_t* __restrict__ oh2, uint32_t* __restrict__ ol2,
    float* __restrict__ Cf)
{
    extern __shared__ char smc[];
    const uint32_t smb = (uint32_t)__cvta_generic_to_shared(smc);
    const int tid = threadIdx.x, wid = tid >> 5, lane = tid & 31;
    const int quad = lane >> 2, tq = lane & 3;
    const int wm = (wid & 3) * 32, wn = (wid >> 2) * 64;
    const int m0 = blockIdx.y * GBM, n0 = blockIdx.x * GBN;
    const int z  = blockIdx.z;
    const __nv_bfloat16* Bh = Wh + (size_t)z * DIM * DIM;
    const __nv_bfloat16* Bl = Wl + (size_t)z * DIM * DIM;
    const float* bias = (MODE == 1) ? bq : (z == 0 ? bq : z == 1 ? bk : bv);

    const int crow = tid >> 2, cch = (tid & 3) * 8;
    const int a_ro = ((lane >> 3) & 1) * 8 + (lane & 7);
    const int a_kb = ((lane >> 4) & 1) * 16;
    const int b_ro = (lane & 7) + ((lane >> 4) & 1) * 8;
    const int b_kb = ((lane >> 3) & 1) * 16;

    float c[2][8][4] = {};

    auto stage_load = [&](int s, int kt) {
        uint32_t sb = smb + s * GSTAGEB;
        #pragma unroll
        for (int i = 0; i < 2; ++i) {
            int r = crow + i * 64;
            size_t ga = (size_t)(m0 + r) * DIM + kt + cch;
            cp16(sb +            r * GPB + cch * 2, Ah + ga);
            cp16(sb +   APLB +   r * GPB + cch * 2, Al + ga);
            size_t gb = (size_t)(n0 + r) * DIM + kt + cch;
            cp16(sb + 2*APLB +   r * GPB + cch * 2, Bh + gb);
            cp16(sb + 3*APLB +   r * GPB + cch * 2, Bl + gb);
        }
        CP_COMMIT();
    };

    stage_load(0, 0);
    int s = 0;
    #pragma unroll 1
    for (int it = 0; it < DIM / GBK; ++it) {
        CP_WAIT0();
        __syncthreads();
        if (it + 1 < DIM / GBK) stage_load(s ^ 1, (it + 1) * GBK);

        uint32_t ab = smb + s * GSTAGEB;
        #pragma unroll
        for (int st = 0; st < 2; ++st) {
            uint32_t ah[2][4], al2[2][4];
            #pragma unroll
            for (int mt = 0; mt < 2; ++mt) {
                uint32_t aa = ab + (wm + mt * 16 + a_ro) * GPB + st * 32 + a_kb;
                ldm_x4(ah[mt], aa);
                ldm_x4(al2[mt], aa + APLB);
            }
            #pragma unroll
            for (int np = 0; np < 4; ++np) {
                uint32_t ba = ab + 2*APLB + (wn + np * 16 + b_ro) * GPB + st * 32 + b_kb;
                uint32_t bh4[4], bl4[4];
                ldm_x4(bh4, ba);
                ldm_x4(bl4, ba + APLB);
                #pragma unroll
                for (int hf = 0; hf < 2; ++hf) {
                    int nt = np * 2 + hf;
                    uint32_t b2h[2] = {bh4[hf*2], bh4[hf*2+1]};
                    uint32_t b2l[2] = {bl4[hf*2], bl4[hf*2+1]};
                    #pragma unroll
                    for (int mt = 0; mt < 2; ++mt) {
                        MMA_BF16(c[mt][nt], ah[mt],  b2h);
                        MMA_BF16(c[mt][nt], ah[mt],  b2l);
                        MMA_BF16(c[mt][nt], al2[mt], b2h);
                    }
                }
            }
        }
        s ^= 1;
    }

    if (MODE == 1) {
        #pragma unroll
        for (int mt = 0; mt < 2; ++mt)
            #pragma unroll
            for (int nt = 0; nt < 8; ++nt) {
                int row = m0 + wm + mt * 16 + quad;
                int col = n0 + wn + nt * 8 + tq * 2;
                float bx = bias[col], by = bias[col + 1];
                *reinterpret_cast<float2*>(Cf + (size_t)row * DIM + col) =
                    make_float2(c[mt][nt][0] + bx, c[mt][nt][1] + by);
                *reinterpret_cast<float2*>(Cf + (size_t)(row + 8) * DIM + col) =
                    make_float2(c[mt][nt][2] + bx, c[mt][nt][3] + by);
            }
    } else {
        float scale = (z == 0) ? 0.125f : 1.0f;
        uint32_t* oh = z == 0 ? oh0 : z == 1 ? oh1 : oh2;
        uint32_t* ol = z == 0 ? ol0 : z == 1 ? ol1 : ol2;
        #pragma unroll
        for (int mt = 0; mt < 2; ++mt)
            #pragma unroll
            for (int nt = 0; nt < 8; ++nt) {
                int row = m0 + wm + mt * 16 + quad;
                int col = n0 + wn + nt * 8 + tq * 2;
                float bx = bias[col], by = bias[col + 1];
                uint32_t hw, lw;
                splitpair((c[mt][nt][0] + bx) * scale, (c[mt][nt][1] + by) * scale, hw, lw);
                size_t w0 = ((size_t)row * DIM + col) >> 1;
                oh[w0] = hw; ol[w0] = lw;
                splitpair((c[mt][nt][2] + bx) * scale, (c[mt][nt][3] + by) * scale, hw, lw);
                size_t w1 = ((size_t)(row + 8) * DIM + col) >> 1;
                oh[w1] = hw; ol[w1] = lw;
            }
    }
}

// ---------------------------------------------------------------------------
// Causal flash attention, 3xBF16 mma.sync on pre-split planes.
// 256 threads per (128-row q block, head, batch); 2 CTAs/SM for latency hiding.
// ---------------------------------------------------------------------------
__global__ __launch_bounds__(256, 2) void attn_mma_kernel(
    const __nv_bfloat16* __restrict__ Qh, const __nv_bfloat16* __restrict__ Ql,
    const __nv_bfloat16* __restrict__ Kh, const __nv_bfloat16* __restrict__ Kl,
    const __nv_bfloat16* __restrict__ Vh, const __nv_bfloat16* __restrict__ Vl,
    uint32_t* __restrict__ Oh, uint32_t* __restrict__ Ol)
{
    extern __shared__ char smc[];
    const uint32_t smb = (uint32_t)__cvta_generic_to_shared(smc);
    const int tid = threadIdx.x, wid = tid >> 5, lane = tid & 31;
    const int quad = lane >> 2, tq = lane & 3;
    const int wm = wid * 16;

    const int qb = (SEQ / QT - 1) - blockIdx.x;    // heavy CTAs first
    const int h  = blockIdx.y;
    const int b  = blockIdx.z;
    const size_t base  = ((size_t)b * SEQ) * DIM + (size_t)h * HD;
    const size_t wbase = base >> 1;

    const int crow = tid >> 3, cch = (tid & 7) * 8;
    auto load_kv = [&](int s, int kb) {
        uint32_t sb = smb + s * ASTAGEB;
        #pragma unroll
        for (int i = 0; i < 2; ++i) {
            int r = crow + i * 32;
            size_t g = base + (size_t)(kb * 64 + r) * DIM + cch;
            cp16(sb +            r * APB + cch * 2, Kh + g);
            cp16(sb +   KPLB +   r * APB + cch * 2, Kl + g);
            cp16(sb + 2*KPLB +   r * APB + cch * 2, Vh + g);
            cp16(sb + 3*KPLB +   r * APB + cch * 2, Vl + g);
        }
        CP_COMMIT();
    };

    load_kv(0, 0);

    // Q fragments straight from gmem planes (prologue only)
    const uint32_t* Qh32 = (const uint32_t*)Qh;
    const uint32_t* Ql32 = (const uint32_t*)Ql;
    uint32_t qh[4][4], ql[4][4];
    {
        size_t r0w = wbase + (size_t)(qb * QT + wm + quad) * (DIM / 2);
        size_t r1w = r0w + 8 * (DIM / 2);
        #pragma unroll
        for (int st = 0; st < 4; ++st) {
            int w0 = st * 8 + tq;
            qh[st][0] = Qh32[r0w + w0];     ql[st][0] = Ql32[r0w + w0];
            qh[st][1] = Qh32[r1w + w0];     ql[st][1] = Ql32[r1w + w0];
            qh[st][2] = Qh32[r0w + w0 + 4]; ql[st][2] = Ql32[r0w + w0 + 4];
            qh[st][3] = Qh32[r1w + w0 + 4]; ql[st][3] = Ql32[r1w + w0 + 4];
        }
    }

    const int k_ro = (lane & 7) + ((lane >> 4) & 1) * 8;   // K non-trans
    const int k_kb = ((lane >> 3) & 1) * 16;
    const int v_ro = (lane & 7) + ((lane >> 3) & 1) * 8;   // V trans
    const int v_db = ((lane >> 4) & 1) * 16;

    float o[8][4] = {};
    float m0v = -1e30f, m1v = -1e30f, l0 = 0.f, l1 = 0.f;

    const int nkb = 2 * qb + 2;
    int s = 0;
    #pragma unroll 1
    for (int kb = 0; kb < nkb; ++kb) {
        CP_WAIT0();
        __syncthreads();
        if (kb + 1 < nkb) load_kv(s ^ 1, kb + 1);

        uint32_t kbh = smb + s * ASTAGEB;
        uint32_t vbh = kbh + 2 * KPLB;

        // ---- S = Q @ K^T ----
        float sv[8][4] = {};
        #pragma unroll
        for (int st = 0; st < 4; ++st) {
            #pragma unroll
            for (int np = 0; np < 4; ++np) {
                uint32_t ba = kbh + (np * 16 + k_ro) * APB + st * 32 + k_kb;
                uint32_t bh4[4], bl4[4];
                ldm_x4(bh4, ba);
                ldm_x4(bl4, ba + KPLB);
                #pragma unroll
                for (int hf = 0; hf < 2; ++hf) {
                    int nt = np * 2 + hf;
                    uint32_t b2h[2] = {bh4[hf*2], bh4[hf*2+1]};
                    uint32_t b2l[2] = {bl4[hf*2], bl4[hf*2+1]};
                    MMA_BF16(sv[nt], qh[st], b2h);
                    MMA_BF16(sv[nt], qh[st], b2l);
                    MMA_BF16(sv[nt], ql[st], b2h);
                }
            }
        }

        // ---- Causal mask ----
        const int coff = kb * 64 - qb * QT;
        if (coff + 63 > 0) {
            int r0 = wm + quad, r1 = r0 + 8;
            #pragma unroll
            for (int nt = 0; nt < 8; ++nt) {
                int c0 = coff + nt * 8 + 2 * tq, c1 = c0 + 1;
                if (c0 > r0) sv[nt][0] = -1e30f;
                if (c1 > r0) sv[nt][1] = -1e30f;
                if (c0 > r1) sv[nt][2] = -1e30f;
                if (c1 > r1) sv[nt][3] = -1e30f;
            }
        }

        // ---- Online softmax ----
        float mx0 = -1e30f, mx1 = -1e30f;
        #pragma unroll
        for (int nt = 0; nt < 8; ++nt) {
            mx0 = fmaxf(mx0, fmaxf(sv[nt][0], sv[nt][1]));
            mx1 = fmaxf(mx1, fmaxf(sv[nt][2], sv[nt][3]));
        }
        mx0 = fmaxf(mx0, __shfl_xor_sync(0xffffffffu, mx0, 1));
        mx0 = fmaxf(mx0, __shfl_xor_sync(0xffffffffu, mx0, 2));
        mx1 = fmaxf(mx1, __shfl_xor_sync(0xffffffffu, mx1, 1));
        mx1 = fmaxf(mx1, __shfl_xor_sync(0xffffffffu, mx1, 2));

        float mn0 = fmaxf(m0v, mx0), mn1 = fmaxf(m1v, mx1);
        float c0 = __expf(m0v - mn0), c1 = __expf(m1v - mn1);
        m0v = mn0; m1v = mn1;

        float rs0 = 0.f, rs1 = 0.f;
        #pragma unroll
        for (int nt = 0; nt < 8; ++nt) {
            sv[nt][0] = __expf(sv[nt][0] - mn0);
            sv[nt][1] = __expf(sv[nt][1] - mn0);
            sv[nt][2] = __expf(sv[nt][2] - mn1);
            sv[nt][3] = __expf(sv[nt][3] - mn1);
            rs0 += sv[nt][0] + sv[nt][1];
            rs1 += sv[nt][2] + sv[nt][3];
        }
        rs0 += __shfl_xor_sync(0xffffffffu, rs0, 1);
        rs0 += __shfl_xor_sync(0xffffffffu, rs0, 2);
        rs1 += __shfl_xor_sync(0xffffffffu, rs1, 1);
        rs1 += __shfl_xor_sync(0xffffffffu, rs1, 2);
        l0 = l0 * c0 + rs0;
        l1 = l1 * c1 + rs1;

        #pragma unroll
        for (int nt = 0; nt < 8; ++nt) {
            o[nt][0] *= c0; o[nt][1] *= c0;
            o[nt][2] *= c1; o[nt][3] *= c1;
        }

        // ---- O += P @ V ---- (P split in regs; V via ldmatrix.trans)
        #pragma unroll
        for (int kt = 0; kt < 4; ++kt) {
            uint32_t ph[4], pl[4];
            splitpair(sv[2*kt][0],   sv[2*kt][1],   ph[0], pl[0]);
            splitpair(sv[2*kt][2],   sv[2*kt][3],   ph[1], pl[1]);
            splitpair(sv[2*kt+1][0], sv[2*kt+1][1], ph[2], pl[2]);
            splitpair(sv[2*kt+1][2], sv[2*kt+1][3], ph[3], pl[3]);
            #pragma unroll
            for (int np = 0; np < 4; ++np) {
                uint32_t va = vbh + (kt * 16 + v_ro) * APB + np * 32 + v_db;
                uint32_t vh4[4], vl4[4];
                ldm_x4t(vh4, va);
                ldm_x4t(vl4, va + KPLB);
                #pragma unroll
                for (int hf = 0; hf < 2; ++hf) {
                    int nt = np * 2 + hf;
                    uint32_t v2h[2] = {vh4[hf*2], vh4[hf*2+1]};
                    uint32_t v2l[2] = {vl4[hf*2], vl4[hf*2+1]};
                    MMA_BF16(o[nt], ph, v2h);
                    MMA_BF16(o[nt], ph, v2l);
                    MMA_BF16(o[nt], pl, v2h);
                }
            }
        }
        s ^= 1;
    }

    // ---- Epilogue: write o hi/lo planes ----
    float inv0 = 1.f / l0, inv1 = 1.f / l1;
    size_t r0w = wbase + (size_t)(qb * QT + wm + quad) * (DIM / 2);
    size_t r1w = r0w + 8 * (DIM / 2);
    #pragma unroll
    for (int nt = 0; nt < 8; ++nt) {
        int cw = nt * 4 + tq;
        uint32_t hw, lw;
        splitpair(o[nt][0] * inv0, o[nt][1] * inv0, hw, lw);
        Oh[r0w + cw] = hw; Ol[r0w + cw] = lw;
        splitpair(o[nt][2] * inv1, o[nt][3] * inv1, hw, lw);
        Oh[r1w + cw] = hw; Ol[r1w + cw] = lw;
    }
}

// ---------------------------------------------------------------------------
extern "C" void kernel_launch(void* const* d_in, const int* in_sizes, int n_in,
                              void* d_out, int out_size)
{
    const float* x  = (const float*)d_in[0];
    const float* Wq = (const float*)d_in[1];
    const float* bq = (const float*)d_in[2];
    const float* Wk = (const float*)d_in[3];
    const float* bk = (const float*)d_in[4];
    const float* Wv = (const float*)d_in[5];
    const float* bv = (const float*)d_in[6];
    const float* Wo = (const float*)d_in[7];
    const float* bo = (const float*)d_in[8];

    __nv_bfloat16 *xh, *xl, *wh, *wl, *qh, *ql, *kh, *kl, *vh, *vl, *oh, *ol;
    cudaGetSymbolAddress((void**)&xh, g_xh); cudaGetSymbolAddress((void**)&xl, g_xl);
    cudaGetSymbolAddress((void**)&wh, g_wh); cudaGetSymbolAddress((void**)&wl, g_wl);
    cudaGetSymbolAddress((void**)&qh, g_qh); cudaGetSymbolAddress((void**)&ql, g_ql);
    cudaGetSymbolAddress((void**)&kh, g_kh); cudaGetSymbolAddress((void**)&kl, g_kl);
    cudaGetSymbolAddress((void**)&vh, g_vh); cudaGetSymbolAddress((void**)&vl, g_vl);
    cudaGetSymbolAddress((void**)&oh, g_oh); cudaGetSymbolAddress((void**)&ol, g_ol);

    // prep: one fused launch for all fp32 -> bf16 hi/lo splits
    int ntot = NX4 + 4 * NW4;
    split_all_kernel<<<(ntot + 255) / 256, 256>>>(
        x, Wq, Wk, Wv, Wo, (uint2*)xh, (uint2*)xl, (uint2*)wh, (uint2*)wl);

    int gsmem = 2 * GSTAGEB;   // 81920
    cudaFuncSetAttribute(gemm_planes_kernel<0>, cudaFuncAttributeMaxDynamicSharedMemorySize, gsmem);
    cudaFuncSetAttribute(gemm_planes_kernel<1>, cudaFuncAttributeMaxDynamicSharedMemorySize, gsmem);

    // fused QKV projections (grid.z selects q/k/v)
    dim3 qkvgrid(DIM / GBN, MTOT / GBM, 3);
    gemm_planes_kernel<0><<<qkvgrid, 256, gsmem>>>(
        xh, xl, wh, wl, bq, bk, bv,
        (uint32_t*)qh, (uint32_t*)ql, (uint32_t*)kh, (uint32_t*)kl,
        (uint32_t*)vh, (uint32_t*)vl, nullptr);

    // attention (2 CTAs/SM)
    int asmem = 2 * ASTAGEB;   // 73728
    cudaFuncSetAttribute(attn_mma_kernel, cudaFuncAttributeMaxDynamicSharedMemorySize, asmem);
    attn_mma_kernel<<<dim3(SEQ / QT, NH, BATCH), 256, asmem>>>(
        qh, ql, kh, kl, vh, vl, (uint32_t*)oh, (uint32_t*)ol);

    // output projection (fp32 out)
    dim3 ogrid(DIM / GBN, MTOT / GBM, 1);
    gemm_planes_kernel<1><<<ogrid, 256, gsmem>>>(
        oh, ol, wh + 3*DIM*DIM, wl + 3*DIM*DIM, bo, nullptr, nullptr,
        nullptr, nullptr, nullptr, nullptr, nullptr, nullptr, (float*)d_out);
}